// round 3
// baseline (speedup 1.0000x reference)
#include <cuda_runtime.h>
#include <math.h>

// Problem constants (fixed by setup_inputs):
//   B=4, H=W=256, C=256, K=1024, window w=5 (25 pixels)
// Inputs (metadata order): source_features (unused by reference!),
//   target_features (B,H,W,C), coarse_positions (B,K,2), Wq,Wk,Wv,Wo (all unused
//   after algebraic collapse — msg is broadcast over the window dim, so every
//   attention layer only adds a constant shift to the final softmax logits).
// Output: refined positions (B,K,2) float32.

#define B_ 4
#define K_ 1024
#define H_ 256
#define W_ 256
#define C_ 256

__global__ __launch_bounds__(256, 8)
void fine_match_kernel(const float* __restrict__ tf,
                       const float* __restrict__ pos,
                       float* __restrict__ out)
{
    // F[c*25 + p] : channel-major flattened 5x5 window (zero-padded borders).
    // corr[n] = sum_j s[j] * F[n*256 + j]  (the reshape-quirk contiguous slice),
    // with s[j] = center pixel = F[j*25 + 12].
    __shared__ float F[25 * 256];   // 25.6 KB
    __shared__ float corr_s[32];

    const int pt  = blockIdx.x;          // 0 .. B*K-1
    const int b   = pt >> 10;            // K = 1024
    const int tid = threadIdx.x;         // 256 threads = channel index for loads

    const float pr = pos[2 * pt + 0];
    const float pc = pos[2 * pt + 1];
    const int r = (int)pr;               // truncation == jnp astype(int32) for >=0
    const int c = (int)pc;

    const float* fb = tf + (size_t)b * H_ * W_ * C_;

    // Gather window: pixel p=(dy,dx) -> original (r-2+dy, c-2+dx), zero if OOB.
    // Gmem: fully coalesced 1 KB per pixel (C innermost). Smem write stride 25
    // -> conflict-free (gcd(25,32)=1).
    #pragma unroll
    for (int p = 0; p < 25; ++p) {
        const int dy = p / 5, dx = p % 5;
        const int rr = r - 2 + dy;
        const int cc = c - 2 + dx;
        float v = 0.0f;
        if (rr >= 0 && rr < H_ && cc >= 0 && cc < W_)
            v = fb[((size_t)rr * W_ + cc) * C_ + tid];
        F[tid * 25 + p] = v;
    }
    __syncthreads();

    const int warp = tid >> 5, lane = tid & 31;

    // 25 dot products of length 256, distributed over 8 warps.
    // Reads F[n*256 + lane + 32t] (bank = lane) and F[j*25+12] (banks distinct
    // across lanes since gcd(25,32)=1) — both conflict-free.
    for (int n = warp; n < 25; n += 8) {
        const float* Fb = F + n * 256;
        float acc = 0.0f;
        #pragma unroll
        for (int t = 0; t < 8; ++t) {
            const int j = lane + 32 * t;
            acc = fmaf(F[j * 25 + 12], Fb[j], acc);
        }
        #pragma unroll
        for (int o = 16; o > 0; o >>= 1)
            acc += __shfl_xor_sync(0xffffffffu, acc, o);
        if (lane == 0) corr_s[n] = acc;
    }
    __syncthreads();

    // Warp 0: softmax over 25 + expected offset.
    if (warp == 0) {
        const float v = (lane < 25) ? corr_s[lane] : -INFINITY;
        float m = v;
        #pragma unroll
        for (int o = 16; o > 0; o >>= 1)
            m = fmaxf(m, __shfl_xor_sync(0xffffffffu, m, o));
        float e = (lane < 25) ? expf(v - m) : 0.0f;
        float ssum = e;
        #pragma unroll
        for (int o = 16; o > 0; o >>= 1)
            ssum += __shfl_xor_sync(0xffffffffu, ssum, o);
        const float prb = e / ssum;      // 0 for lane >= 25 (e==0)

        // offsets: linspace(-3, 2, 5) = -3 + 1.25*i (exact in fp32)
        // offsets[n] = ( off1d[n/5], off1d[n%5] )
        const int ir = lane / 5;
        const int ic = lane - ir * 5;
        float dr = prb * (-3.0f + 1.25f * (float)ir);
        float dc = prb * (-3.0f + 1.25f * (float)ic);
        #pragma unroll
        for (int o = 16; o > 0; o >>= 1) {
            dr += __shfl_xor_sync(0xffffffffu, dr, o);
            dc += __shfl_xor_sync(0xffffffffu, dc, o);
        }
        if (lane == 0) {
            out[2 * pt + 0] = pr + dr;
            out[2 * pt + 1] = pc + dc;
        }
    }
}

extern "C" void kernel_launch(void* const* d_in, const int* in_sizes, int n_in,
                              void* d_out, int out_size)
{
    (void)in_sizes; (void)n_in; (void)out_size;
    // metadata order: 0=source_features (unused), 1=target_features,
    // 2=coarse_positions, 3..6 = Wq,Wk,Wv,Wo (unused after collapse)
    const float* tf  = (const float*)d_in[1];
    const float* pos = (const float*)d_in[2];
    float* out = (float*)d_out;

    fine_match_kernel<<<B_ * K_, 256>>>(tf, pos, out);
}